// round 3
// baseline (speedup 1.0000x reference)
#include <cuda_runtime.h>
#include <cuda_bf16.h>

#define NQ      10
#define DIM     1024
#define NLAYERS 4
#define NTHREADS 256

__device__ __forceinline__ float2 cmul(float2 a, float2 b) {
    return make_float2(fmaf(a.x, b.x, -a.y * b.y), fmaf(a.x, b.y, a.y * b.x));
}
__device__ __forceinline__ float2 cadd(float2 a, float2 b) { return make_float2(a.x + b.x, a.y + b.y); }
__device__ __forceinline__ float2 csub(float2 a, float2 b) { return make_float2(a.x - b.x, a.y - b.y); }
__device__ __forceinline__ float2 cscale(float s, float2 a) { return make_float2(s * a.x, s * a.y); }

__global__ __launch_bounds__(NTHREADS, 8)
void quantum_layer_kernel(const float* __restrict__ x,
                          const float* __restrict__ weight,
                          float* __restrict__ out)
{
    __shared__ float2 st[DIM];            // 8 KB statevector
    __shared__ float2 M[NQ][4];           // fused 2x2 gate per wire
    __shared__ unsigned short perm[DIM];  // CNOT-ring permutation LUT
    __shared__ float wsum[NTHREADS / 32][NQ];

    const int b   = blockIdx.x;
    const int tid = threadIdx.x;

    // ---- init state |0...0>  +  build CNOT-ring permutation LUT (layer-invariant)
    #pragma unroll
    for (int k = 0; k < DIM / NTHREADS; ++k) {
        int j = tid + k * NTHREADS;
        st[j] = make_float2(j == 0 ? 1.0f : 0.0f, 0.0f);
        // out[j] = in[ P1(P2(...P10(j))) ]; apply CNOTs in reverse application order.
        // Application order: CNOT(i,i+1) for i=0..8, then CNOT(9,0).
        // wire w -> bit position (9-w).
        int src = j;
        src ^= ((src & 1) << 9);                       // CNOT(9,0): cb=0, tb=9
        #pragma unroll
        for (int q = 8; q >= 0; --q) {                 // CNOT(q, q+1): cb=9-q, tb=8-q
            int cb = 9 - q, tb = 8 - q;
            src ^= (((src >> cb) & 1) << tb);
        }
        perm[j] = (unsigned short)src;
    }
    __syncthreads();

    for (int l = 0; l < NLAYERS; ++l) {
        // ---- fused per-wire matrix: M = RZ(th3) * RY(th2) * RZ(th1) * RY(th0)
        if (tid < NQ) {
            const int i = tid;
            float th0 = tanhf(x[b * NQ + i]) * 3.14159265358979323846f;   // batched RY angle
            float th1 = weight[(l * NQ + i) * 3 + 0];
            float th2 = weight[(l * NQ + i) * 3 + 1];
            float th3 = weight[(l * NQ + i) * 3 + 2];
            float s0, c0, s1, c1, s2, c2, s3, c3;
            __sincosf(0.5f * th0, &s0, &c0);
            __sincosf(0.5f * th1, &s1, &c1);
            __sincosf(0.5f * th2, &s2, &c2);
            __sincosf(0.5f * th3, &s3, &c3);
            float2 d1m = make_float2(c1, -s1), d1p = make_float2(c1, s1);
            float2 d3m = make_float2(c3, -s3), d3p = make_float2(c3, s3);
            // row0 of RY2 * (RZ1 * RY0): [ c2*c0*d1m - s2*s0*d1p ,  -c2*s0*d1m - s2*c0*d1p ]
            // row1:                      [ s2*c0*d1m + c2*s0*d1p ,  -s2*s0*d1m + c2*c0*d1p ]
            float2 m00 = cmul(d3m, csub(cscale(c2 * c0, d1m), cscale(s2 * s0, d1p)));
            float2 m01 = cmul(d3m, csub(cscale(-c2 * s0, d1m), cscale(s2 * c0, d1p)));
            float2 m10 = cmul(d3p, cadd(cscale(s2 * c0, d1m), cscale(c2 * s0, d1p)));
            float2 m11 = cmul(d3p, csub(cscale(c2 * c0, d1p), cscale(s2 * s0, d1m)));
            M[i][0] = m00; M[i][1] = m01; M[i][2] = m10; M[i][3] = m11;
        }
        __syncthreads();

        // ---- 10 fused single-qubit gates
        #pragma unroll
        for (int wq = 0; wq < NQ; ++wq) {
            const int bp = 9 - wq;
            const int lomask = (1 << bp) - 1;
            const float2 m00 = M[wq][0], m01 = M[wq][1], m10 = M[wq][2], m11 = M[wq][3];
            #pragma unroll
            for (int k = 0; k < 2; ++k) {
                int p  = tid + k * NTHREADS;                  // pair index in [0,512)
                int i0 = ((p & ~lomask) << 1) | (p & lomask); // insert 0 at bit bp
                int i1 = i0 | (1 << bp);
                float2 a0 = st[i0], a1 = st[i1];
                float2 b0 = cadd(cmul(m00, a0), cmul(m01, a1));
                float2 b1 = cadd(cmul(m10, a0), cmul(m11, a1));
                st[i0] = b0;                                  // pairs disjoint per gate
                st[i1] = b1;
            }
            __syncthreads();
        }

        // ---- CNOT ring as a single permutation (gather to regs, sync, scatter)
        float2 r[DIM / NTHREADS];
        #pragma unroll
        for (int k = 0; k < DIM / NTHREADS; ++k)
            r[k] = st[perm[tid + k * NTHREADS]];
        __syncthreads();
        #pragma unroll
        for (int k = 0; k < DIM / NTHREADS; ++k)
            st[tid + k * NTHREADS] = r[k];
        __syncthreads();
    }

    // ---- measurement: <Z_i> = sum_j |amp_j|^2 * (1 - 2*bit_i(j))
    float acc[NQ];
    #pragma unroll
    for (int i = 0; i < NQ; ++i) acc[i] = 0.0f;
    #pragma unroll
    for (int k = 0; k < DIM / NTHREADS; ++k) {
        int j = tid + k * NTHREADS;
        float2 a = st[j];
        float p = fmaf(a.x, a.x, a.y * a.y);
        #pragma unroll
        for (int i = 0; i < NQ; ++i)
            acc[i] += ((j >> (9 - i)) & 1) ? -p : p;
    }
    #pragma unroll
    for (int off = 16; off > 0; off >>= 1) {
        #pragma unroll
        for (int i = 0; i < NQ; ++i)
            acc[i] += __shfl_xor_sync(0xffffffffu, acc[i], off);
    }
    const int warp = tid >> 5, lane = tid & 31;
    if (lane == 0) {
        #pragma unroll
        for (int i = 0; i < NQ; ++i) wsum[warp][i] = acc[i];
    }
    __syncthreads();
    if (tid < NQ) {
        float s = 0.0f;
        #pragma unroll
        for (int wp = 0; wp < NTHREADS / 32; ++wp) s += wsum[wp][tid];
        out[b * NQ + tid] = s;
    }
}

extern "C" void kernel_launch(void* const* d_in, const int* in_sizes, int n_in,
                              void* d_out, int out_size) {
    const float* x      = (const float*)d_in[0];   // (16384, 10) float32
    const float* weight = (const float*)d_in[1];   // (4, 10, 3)  float32
    float* out          = (float*)d_out;           // (16384, 10) float32
    const int batch = in_sizes[0] / NQ;
    quantum_layer_kernel<<<batch, NTHREADS>>>(x, weight, out);
}

// round 5
// speedup vs baseline: 2.1709x; 2.1709x over previous
#include <cuda_runtime.h>

#define NQ       10
#define DIM      1024
#define NLAYERS  4
#define WPB      2            // warps per block; each warp = 2 batch elements
#define NT       (WPB * 32)
#define PI_F     3.14159265358979323846f

typedef unsigned long long u64;

// ---- packed f32x2 helpers (batch0 in lo, batch1 in hi) ----
__device__ __forceinline__ u64 pk2(float lo, float hi) {
    u64 r; asm("mov.b64 %0, {%1, %2};" : "=l"(r) : "f"(lo), "f"(hi)); return r;
}
__device__ __forceinline__ void upk2(u64 v, float& lo, float& hi) {
    asm("mov.b64 {%0, %1}, %2;" : "=f"(lo), "=f"(hi) : "l"(v));
}
__device__ __forceinline__ u64 fma2(u64 a, u64 b, u64 c) {
    u64 d; asm("fma.rn.f32x2 %0, %1, %2, %3;" : "=l"(d) : "l"(a), "l"(b), "l"(c)); return d;
}
__device__ __forceinline__ u64 mul2(u64 a, u64 b) {
    u64 d; asm("mul.rn.f32x2 %0, %1, %2;" : "=l"(d) : "l"(a), "l"(b)); return d;
}
__device__ __forceinline__ u64 add2(u64 a, u64 b) {
    u64 d; asm("add.rn.f32x2 %0, %1, %2;" : "=l"(d) : "l"(a), "l"(b)); return d;
}

// ---- scalar complex helpers for matrix construction ----
__device__ __forceinline__ float2 cmul(float2 a, float2 b) {
    return make_float2(fmaf(a.x, b.x, -a.y * b.y), fmaf(a.x, b.y, a.y * b.x));
}
__device__ __forceinline__ float2 cadd(float2 a, float2 b) { return make_float2(a.x + b.x, a.y + b.y); }
__device__ __forceinline__ float2 csub(float2 a, float2 b) { return make_float2(a.x - b.x, a.y - b.y); }
__device__ __forceinline__ float2 cscale(float s, float2 a) { return make_float2(s * a.x, s * a.y); }

// fused 2x2 gate on one amplitude pair, packed over 2 batch elements.
// c layout: [r00,i00,n00, r01,i01,n01, r10,i10,n10, r11,i11,n11] (n = -i)
__device__ __forceinline__ void gate2(const u64* __restrict__ c,
                                      u64& a0r, u64& a0i, u64& a1r, u64& a1i) {
    u64 b0r = fma2(c[0], a0r, fma2(c[2], a0i, fma2(c[3],  a1r, mul2(c[5],  a1i))));
    u64 b0i = fma2(c[0], a0i, fma2(c[1], a0r, fma2(c[3],  a1i, mul2(c[4],  a1r))));
    u64 b1r = fma2(c[6], a0r, fma2(c[8], a0i, fma2(c[9],  a1r, mul2(c[11], a1i))));
    u64 b1i = fma2(c[6], a0i, fma2(c[7], a0r, fma2(c[9],  a1i, mul2(c[10], a1r))));
    a0r = b0r; a0i = b0i; a1r = b1r; a1i = b1i;
}

__global__ __launch_bounds__(NT)
void quantum_layer_kernel(const float* __restrict__ x,
                          const float* __restrict__ weight,
                          float* __restrict__ out)
{
    // per-warp statevector (2 batches packed): float4 = (re_b0, re_b1, im_b0, im_b1)
    __shared__ float4 sv[WPB][DIM];                    // 32 KB
    __shared__ u64 wm[WPB][NLAYERS][NQ][12];           // fused gate coeffs, packed
    __shared__ unsigned short scat[DIM];               // swizzled scatter LUT for CNOT ring

    const int tid = threadIdx.x;
    const int wp  = tid >> 5;
    const int t   = tid & 31;
    const int pairId = blockIdx.x * WPB + wp;
    const int b0 = pairId * 2, b1 = b0 + 1;

    // ---- CNOT-ring permutation: st'[j] = st[p(j)]. Build scatter LUT:
    // scat[p(j)] = phys(j), phys(v) = v ^ ((v>>5)&31)  (bank-conflict swizzle)
    for (int j = tid; j < DIM; j += NT) {
        int src = j;
        src ^= (src & 1) << 9;                         // CNOT(9,0)
        #pragma unroll
        for (int q = 8; q >= 0; --q) {                 // CNOT(q,q+1)
            int cb = 9 - q, tb = 8 - q;
            src ^= ((src >> cb) & 1) << tb;
        }
        scat[src] = (unsigned short)(j ^ ((j >> 5) & 31));
    }

    // ---- fused per-wire matrices M = RZ(w2)*RY(w1)*RZ(w0)*RY(tanh(x)*pi), all layers
    if (t < NQ) {
        const int w = t;
        float ang[2];
        ang[0] = tanhf(x[b0 * NQ + w]) * PI_F;
        ang[1] = tanhf(x[b1 * NQ + w]) * PI_F;
        for (int l = 0; l < NLAYERS; ++l) {
            float th1 = weight[(l * NQ + w) * 3 + 0];
            float th2 = weight[(l * NQ + w) * 3 + 1];
            float th3 = weight[(l * NQ + w) * 3 + 2];
            float2 m[2][4];
            #pragma unroll
            for (int bb = 0; bb < 2; ++bb) {
                float s0, c0, s1, c1, s2, c2, s3, c3;
                __sincosf(0.5f * ang[bb], &s0, &c0);
                __sincosf(0.5f * th1, &s1, &c1);
                __sincosf(0.5f * th2, &s2, &c2);
                __sincosf(0.5f * th3, &s3, &c3);
                float2 d1m = make_float2(c1, -s1), d1p = make_float2(c1, s1);
                float2 d3m = make_float2(c3, -s3), d3p = make_float2(c3, s3);
                m[bb][0] = cmul(d3m, csub(cscale(c2 * c0, d1m), cscale(s2 * s0, d1p)));
                m[bb][1] = cmul(d3m, csub(cscale(-c2 * s0, d1m), cscale(s2 * c0, d1p)));
                m[bb][2] = cmul(d3p, cadd(cscale(s2 * c0, d1m), cscale(c2 * s0, d1p)));
                m[bb][3] = cmul(d3p, csub(cscale(c2 * c0, d1p), cscale(s2 * s0, d1m)));
            }
            u64* dst = wm[wp][l][w];
            #pragma unroll
            for (int e = 0; e < 4; ++e) {
                dst[e * 3 + 0] = pk2(m[0][e].x,  m[1][e].x);   // re
                dst[e * 3 + 1] = pk2(m[0][e].y,  m[1][e].y);   // im
                dst[e * 3 + 2] = pk2(-m[0][e].y, -m[1][e].y);  // -im
            }
        }
    }
    __syncthreads();

    // ---- state in registers: thread t holds 32 amps (its 5-bit subcube)
    u64 re[32], im[32];
    // init |0...0>: only amp j=0 nonzero (thread 0, reg 0)
    #pragma unroll
    for (int i = 0; i < 32; ++i) { re[i] = 0ULL; im[i] = 0ULL; }
    if (t == 0) re[0] = pk2(1.0f, 1.0f);

    const unsigned fullmask = 0xffffffffu;

    for (int l = 0; l < NLAYERS; ++l) {
        // ===== sweep A: gate bits 0..4 (wires 9..5). amps j=(t<<5)|i, reg index i
        if (l > 0) {
            #pragma unroll
            for (int i = 0; i < 32; ++i) {
                float4 v = sv[wp][(t << 5) | (i ^ t)];
                re[i] = pk2(v.x, v.y); im[i] = pk2(v.z, v.w);
            }
        }
        #pragma unroll
        for (int g = 0; g < 5; ++g) {
            u64 c[12];
            const u64* C = wm[wp][l][9 - g];
            #pragma unroll
            for (int q = 0; q < 12; ++q) c[q] = C[q];
            const int bm = 1 << g, lo = bm - 1;
            #pragma unroll
            for (int p = 0; p < 16; ++p) {
                const int i0 = ((p & ~lo) << 1) | (p & lo);
                const int i1 = i0 | bm;
                gate2(c, re[i0], im[i0], re[i1], im[i1]);
            }
        }
        // store sweep A result (own contiguous range, swizzled)
        #pragma unroll
        for (int i = 0; i < 32; ++i) {
            float4 v; upk2(re[i], v.x, v.y); upk2(im[i], v.z, v.w);
            sv[wp][(t << 5) | (i ^ t)] = v;
        }
        __syncwarp(fullmask);

        // ===== sweep B: gate bits 5..9 (wires 4..0). amps x=(i<<5)|t, reg index i
        #pragma unroll
        for (int i = 0; i < 32; ++i) {
            float4 v = sv[wp][(i << 5) | (t ^ i)];
            re[i] = pk2(v.x, v.y); im[i] = pk2(v.z, v.w);
        }
        #pragma unroll
        for (int g = 0; g < 5; ++g) {
            u64 c[12];
            const u64* C = wm[wp][l][4 - g];
            #pragma unroll
            for (int q = 0; q < 12; ++q) c[q] = C[q];
            const int bm = 1 << g, lo = bm - 1;
            #pragma unroll
            for (int p = 0; p < 16; ++p) {
                const int i0 = ((p & ~lo) << 1) | (p & lo);
                const int i1 = i0 | bm;
                gate2(c, re[i0], im[i0], re[i1], im[i1]);
            }
        }
        // CNOT ring folded into the store: scatter amp x to phys(pinv(x)).
        // Last layer: skip store — measurement applies the permutation via signs.
        if (l < NLAYERS - 1) {
            #pragma unroll
            for (int i = 0; i < 32; ++i) {
                int d = scat[(i << 5) | t];
                float4 v; upk2(re[i], v.x, v.y); upk2(im[i], v.z, v.w);
                sv[wp][d] = v;
            }
            __syncwarp(fullmask);
        }
    }

    // ---- measurement: out_w = sum_x |amp_x|^2 * (-1)^{bit_{9-w}(pinv(x))}
    // pinv rows: bit k of pinv(x) = parity(x & mask_k):
    //   mask_0 = 0x3FF, mask_k(1..8) = bits k..9, mask_9 = 0x1FF
    #pragma unroll
    for (int i = 0; i < 32; ++i)
        re[i] = fma2(re[i], re[i], mul2(im[i], im[i]));   // packed |amp|^2

    const u64 pone = pk2(1.0f, 1.0f), none = pk2(-1.0f, -1.0f);
    #pragma unroll
    for (int w = 0; w < NQ; ++w) {
        const int k = 9 - w;
        const unsigned mask = (k == 0) ? 0x3FFu : (k == 9 ? 0x1FFu : (0x3FFu & ~((1u << k) - 1u)));
        const unsigned mh = (mask >> 5) & 31u, ml = mask & 31u;
        u64 acc = 0ULL;   // packed (+0.f, +0.f)
        #pragma unroll
        for (int i = 0; i < 32; ++i)
            acc = fma2(re[i], (__popc((unsigned)i & mh) & 1) ? none : pone, acc);
        if (__popc((unsigned)t & ml) & 1) acc = mul2(acc, none);
        #pragma unroll
        for (int off = 16; off; off >>= 1) {
            u64 o = __shfl_xor_sync(fullmask, acc, off);
            acc = add2(acc, o);
        }
        float ra, rb; upk2(acc, ra, rb);
        if (t == 0) out[b0 * NQ + w] = ra;
        if (t == 1) out[b1 * NQ + w] = rb;
    }
}

extern "C" void kernel_launch(void* const* d_in, const int* in_sizes, int n_in,
                              void* d_out, int out_size) {
    const float* x      = (const float*)d_in[0];   // (16384, 10) float32
    const float* weight = (const float*)d_in[1];   // (4, 10, 3)  float32
    float* out          = (float*)d_out;           // (16384, 10) float32
    const int batch  = in_sizes[0] / NQ;
    const int blocks = batch / (2 * WPB);          // 2 batch elems per warp
    quantum_layer_kernel<<<blocks, NT>>>(x, weight, out);
}

// round 7
// speedup vs baseline: 2.5349x; 1.1677x over previous
#include <cuda_runtime.h>

#define NQ       10
#define DIM      1024
#define NLAYERS  4
#define NT       64           // 64 threads = 2 warps = one state-pair (2 batch elems)
#define PI_F     3.14159265358979323846f

typedef unsigned long long u64;

// ---- packed f32x2 helpers (batch0 in lo, batch1 in hi) ----
__device__ __forceinline__ u64 pk2(float lo, float hi) {
    u64 r; asm("mov.b64 %0, {%1, %2};" : "=l"(r) : "f"(lo), "f"(hi)); return r;
}
__device__ __forceinline__ void upk2(u64 v, float& lo, float& hi) {
    asm("mov.b64 {%0, %1}, %2;" : "=f"(lo), "=f"(hi) : "l"(v));
}
__device__ __forceinline__ u64 fma2(u64 a, u64 b, u64 c) {
    u64 d; asm("fma.rn.f32x2 %0, %1, %2, %3;" : "=l"(d) : "l"(a), "l"(b), "l"(c)); return d;
}
__device__ __forceinline__ u64 mul2(u64 a, u64 b) {
    u64 d; asm("mul.rn.f32x2 %0, %1, %2;" : "=l"(d) : "l"(a), "l"(b)); return d;
}
__device__ __forceinline__ u64 add2(u64 a, u64 b) {
    u64 d; asm("add.rn.f32x2 %0, %1, %2;" : "=l"(d) : "l"(a), "l"(b)); return d;
}
__device__ __forceinline__ u64 neg2(u64 v) { return v ^ 0x8000000080000000ULL; }

// ---- scalar complex helpers (matrix construction only) ----
__device__ __forceinline__ float2 cmul(float2 a, float2 b) {
    return make_float2(fmaf(a.x, b.x, -a.y * b.y), fmaf(a.x, b.y, a.y * b.x));
}
__device__ __forceinline__ float2 cadd(float2 a, float2 b) { return make_float2(a.x + b.x, a.y + b.y); }
__device__ __forceinline__ float2 csub(float2 a, float2 b) { return make_float2(a.x - b.x, a.y - b.y); }
__device__ __forceinline__ float2 cscale(float s, float2 a) { return make_float2(s * a.x, s * a.y); }

// smem swizzle: phys(j) = j ^ s(j>>5), s(a) = (a&15) | ((a&8)<<1).
// Conflict-free for all three transpose patterns (verified per warp).
__device__ __forceinline__ int phys(int j) {
    int a = j >> 5;
    return j ^ ((a & 15) | ((a & 8) << 1));
}

// fused 2x2 gate on one amplitude pair, packed over 2 batch elements.
// c layout: [r00,i00,n00, r01,i01,n01, r10,i10,n10, r11,i11,n11] (n = -i)
__device__ __forceinline__ void gate2(const u64* __restrict__ c,
                                      u64& a0r, u64& a0i, u64& a1r, u64& a1i) {
    u64 b0r = fma2(c[0], a0r, fma2(c[2], a0i, fma2(c[3],  a1r, mul2(c[5],  a1i))));
    u64 b0i = fma2(c[0], a0i, fma2(c[1], a0r, fma2(c[3],  a1i, mul2(c[4],  a1r))));
    u64 b1r = fma2(c[6], a0r, fma2(c[8], a0i, fma2(c[9],  a1r, mul2(c[11], a1i))));
    u64 b1i = fma2(c[6], a0i, fma2(c[7], a0r, fma2(c[9],  a1i, mul2(c[10], a1r))));
    a0r = b0r; a0i = b0i; a1r = b1r; a1i = b1i;
}

// apply gate with coeffs C on register bit g (8 disjoint pairs among 16 regs)
#define APPLY_GATE(Cptr, g) do {                                            \
    u64 c_[12]; const u64* C_ = (Cptr);                                     \
    _Pragma("unroll") for (int q_ = 0; q_ < 12; ++q_) c_[q_] = C_[q_];      \
    const int bm_ = 1 << (g), lo_ = bm_ - 1;                                \
    _Pragma("unroll") for (int p_ = 0; p_ < 8; ++p_) {                      \
        const int i0_ = ((p_ & ~lo_) << 1) | (p_ & lo_);                    \
        const int i1_ = i0_ | bm_;                                          \
        gate2(c_, re[i0_], im[i0_], re[i1_], im[i1_]);                      \
    }                                                                       \
} while (0)

__global__ __launch_bounds__(NT)
void quantum_layer_kernel(const float* __restrict__ x,
                          const float* __restrict__ weight,
                          float* __restrict__ out)
{
    __shared__ float4 sv[DIM];               // 16 KB: (re_b0, re_b1, im_b0, im_b1)
    __shared__ u64 wm[NLAYERS][NQ][12];      // fused gate coeffs, packed: 3.75 KB
    __shared__ unsigned short scat[DIM];     // CNOT-ring scatter LUT (swizzled): 2 KB
    __shared__ u64 wred[2][NQ];              // cross-warp measurement reduce

    const int t  = threadIdx.x;              // 0..63
    const int b0 = blockIdx.x * 2, b1 = b0 + 1;

    // ---- CNOT-ring: st'[j] = st[p(j)]. scat[p(j)] = phys(j).
    for (int j = t; j < DIM; j += NT) {
        int src = j;
        src ^= (src & 1) << 9;                         // CNOT(9,0)
        #pragma unroll
        for (int q = 8; q >= 0; --q) {                 // CNOT(q,q+1)
            int cb = 9 - q, tb = 8 - q;
            src ^= ((src >> cb) & 1) << tb;
        }
        scat[src] = (unsigned short)phys(j);
    }

    // ---- fused per-wire matrices M = RZ(w2)*RY(w1)*RZ(w0)*RY(tanh(x)*pi)
    if (t < NQ) {
        const int w = t;
        float ang[2];
        ang[0] = tanhf(x[b0 * NQ + w]) * PI_F;
        ang[1] = tanhf(x[b1 * NQ + w]) * PI_F;
        for (int l = 0; l < NLAYERS; ++l) {
            float th1 = weight[(l * NQ + w) * 3 + 0];
            float th2 = weight[(l * NQ + w) * 3 + 1];
            float th3 = weight[(l * NQ + w) * 3 + 2];
            float2 m[2][4];
            #pragma unroll
            for (int bb = 0; bb < 2; ++bb) {
                float s0, c0, s1, c1, s2, c2, s3, c3;
                __sincosf(0.5f * ang[bb], &s0, &c0);
                __sincosf(0.5f * th1, &s1, &c1);
                __sincosf(0.5f * th2, &s2, &c2);
                __sincosf(0.5f * th3, &s3, &c3);
                float2 d1m = make_float2(c1, -s1), d1p = make_float2(c1, s1);
                float2 d3m = make_float2(c3, -s3), d3p = make_float2(c3, s3);
                m[bb][0] = cmul(d3m, csub(cscale(c2 * c0, d1m), cscale(s2 * s0, d1p)));
                m[bb][1] = cmul(d3m, csub(cscale(-c2 * s0, d1m), cscale(s2 * c0, d1p)));
                m[bb][2] = cmul(d3p, cadd(cscale(s2 * c0, d1m), cscale(c2 * s0, d1p)));
                m[bb][3] = cmul(d3p, csub(cscale(c2 * c0, d1p), cscale(s2 * s0, d1m)));
            }
            u64* dst = wm[l][w];
            #pragma unroll
            for (int e = 0; e < 4; ++e) {
                dst[e * 3 + 0] = pk2(m[0][e].x,  m[1][e].x);   // re
                dst[e * 3 + 1] = pk2(m[0][e].y,  m[1][e].y);   // im
                dst[e * 3 + 2] = pk2(-m[0][e].y, -m[1][e].y);  // -im
            }
        }
    }
    __syncthreads();

    // ---- state: 16 amps/thread, three arrangements per layer:
    //  A: j = (t<<4)|r            gates on bits 0..3  (wires 9..6)
    //  B: j = (t>>4)<<8|(r<<4)|(t&15)  gates on bits 4..7 (wires 5..2)
    //  C: j = (r<<6)|t            gates on bits 8,9 (reg bits 2,3; wires 1,0)
    u64 re[16], im[16];

    const int tbhi = (t >> 4) << 8, tblo = t & 15;

    for (int l = 0; l < NLAYERS; ++l) {
        if (l == 0) {
            // |0..0>: A-group result is a gate-column product on thread 0 only
            #pragma unroll
            for (int i = 0; i < 16; ++i) { re[i] = 0ULL; im[i] = 0ULL; }
            if (t == 0) {
                #pragma unroll
                for (int r = 0; r < 16; ++r) {
                    u64 ar = pk2(1.0f, 1.0f), ai = 0ULL;
                    #pragma unroll
                    for (int g = 0; g < 4; ++g) {
                        const u64* C = wm[0][9 - g];
                        const int sel = (r >> g) & 1;
                        u64 br = C[6 * sel], bi = C[6 * sel + 1];
                        u64 nr = fma2(ar, br, neg2(mul2(ai, bi)));
                        u64 ni = fma2(ar, bi, mul2(ai, br));
                        ar = nr; ai = ni;
                    }
                    re[r] = ar; im[r] = ai;
                }
            }
        } else {
            // load A (own slots — written by scat store of previous layer)
            #pragma unroll
            for (int r = 0; r < 16; ++r) {
                float4 v = sv[phys((t << 4) | r)];
                re[r] = pk2(v.x, v.y); im[r] = pk2(v.z, v.w);
            }
            APPLY_GATE(wm[l][9], 0);
            APPLY_GATE(wm[l][8], 1);
            APPLY_GATE(wm[l][7], 2);
            APPLY_GATE(wm[l][6], 3);
        }
        // store A (same per-thread slots as the A load: no hazard)
        #pragma unroll
        for (int r = 0; r < 16; ++r) {
            float4 v; upk2(re[r], v.x, v.y); upk2(im[r], v.z, v.w);
            sv[phys((t << 4) | r)] = v;
        }
        __syncthreads();

        // ---- group B
        #pragma unroll
        for (int r = 0; r < 16; ++r) {
            float4 v = sv[phys(tbhi | (r << 4) | tblo)];
            re[r] = pk2(v.x, v.y); im[r] = pk2(v.z, v.w);
        }
        APPLY_GATE(wm[l][5], 0);
        APPLY_GATE(wm[l][4], 1);
        APPLY_GATE(wm[l][3], 2);
        APPLY_GATE(wm[l][2], 3);
        #pragma unroll
        for (int r = 0; r < 16; ++r) {
            float4 v; upk2(re[r], v.x, v.y); upk2(im[r], v.z, v.w);
            sv[phys(tbhi | (r << 4) | tblo)] = v;
        }
        __syncthreads();

        // ---- group C
        #pragma unroll
        for (int r = 0; r < 16; ++r) {
            float4 v = sv[phys((r << 6) | t)];
            re[r] = pk2(v.x, v.y); im[r] = pk2(v.z, v.w);
        }
        APPLY_GATE(wm[l][1], 2);
        APPLY_GATE(wm[l][0], 3);
        if (l < NLAYERS - 1) {
            __syncthreads();   // all C loads done before permuted scatter
            #pragma unroll
            for (int r = 0; r < 16; ++r) {
                float4 v; upk2(re[r], v.x, v.y); upk2(im[r], v.z, v.w);
                sv[scat[(r << 6) | t]] = v;
            }
            __syncthreads();
        }
    }

    // ---- measurement in arrangement C: amp x = (r<<6)|t.
    // Final CNOT ring folded into signs: bit k of pinv(x) = parity(x & mask_k),
    // mask_k = bits k..9 (k=0..8), mask_9 = 0x1FF.
    #pragma unroll
    for (int i = 0; i < 16; ++i)
        re[i] = fma2(re[i], re[i], mul2(im[i], im[i]));   // packed |amp|^2

    const u64 pone = pk2(1.0f, 1.0f), none = pk2(-1.0f, -1.0f);
    const int warp = t >> 5;
    const unsigned fullmask = 0xffffffffu;
    #pragma unroll
    for (int w = 0; w < NQ; ++w) {
        const int k = 9 - w;
        const unsigned mask = (k == 9) ? 0x1FFu : (0x3FFu & ~((1u << k) - 1u));
        const unsigned mr = (mask >> 6) & 15u, mt = mask & 63u;
        u64 acc = 0ULL;
        #pragma unroll
        for (int r = 0; r < 16; ++r)
            acc = fma2(re[r], (__popc((unsigned)r & mr) & 1) ? none : pone, acc);
        if (__popc((unsigned)t & mt) & 1) acc = neg2(acc);
        #pragma unroll
        for (int off = 16; off; off >>= 1) {
            u64 o = __shfl_xor_sync(fullmask, acc, off);
            acc = add2(acc, o);
        }
        if ((t & 31) == 0) wred[warp][w] = acc;
    }
    __syncthreads();
    if (t < NQ) {
        u64 s = add2(wred[0][t], wred[1][t]);
        float ra, rb; upk2(s, ra, rb);
        out[b0 * NQ + t] = ra;
        out[b1 * NQ + t] = rb;
    }
}

extern "C" void kernel_launch(void* const* d_in, const int* in_sizes, int n_in,
                              void* d_out, int out_size) {
    const float* x      = (const float*)d_in[0];   // (16384, 10) float32
    const float* weight = (const float*)d_in[1];   // (4, 10, 3)  float32
    float* out          = (float*)d_out;           // (16384, 10) float32
    const int batch  = in_sizes[0] / NQ;
    const int blocks = batch / 2;                  // 2 batch elems per block
    quantum_layer_kernel<<<blocks, NT>>>(x, weight, out);
}